// round 1
// baseline (speedup 1.0000x reference)
#include <cuda_runtime.h>

// ---------------- problem constants ----------------
#define DIM      4096
#define EXPERTS  64
#define MAX_T    8192
#define BT       64          // tokens per block (pass1/pass3 tiling)
#define BK       16          // k-chunk
#define NTHREADS 128
#define MAXNB    (MAX_T / BT)

// ---------------- scratch (no allocation allowed) ----------------
__device__ float g_me[EXPERTS];
__device__ int   g_indices[MAX_T];
__device__ int   g_blockCounts[MAXNB * EXPERTS];
__device__ int   g_blockOffsets[MAXNB * EXPERTS];

// ---------------- pass 0: zero me ----------------
__global__ void init_kernel() {
    if (threadIdx.x < EXPERTS) g_me[threadIdx.x] = 0.0f;
}

// ---------------- pass 1: GEMM + argmax + softmax + histograms ----------------
// smem layout: union of {As[BT][20] + Ws[BK][68]} and {Ls[BT][68]}
#define AS_STRIDE 20
#define WS_STRIDE 68
#define LS_STRIDE 68
#define SMEM_FLOATS (BT * LS_STRIDE)   // 4352 floats (>= 64*20+16*68 = 2368)

__global__ __launch_bounds__(NTHREADS) void gate_main(
    const float* __restrict__ A,   // [T][DIM]
    const float* __restrict__ W,   // [EXPERTS][DIM]
    float* __restrict__ out,       // [1 + 3T]
    int T)
{
    __shared__ __align__(16) float smem[SMEM_FLOATS];
    __shared__ float ms[BT];
    __shared__ float sums[BT];
    __shared__ int   cnt_s[EXPERTS];

    float* As = smem;                      // [BT][AS_STRIDE]
    float* Ws = smem + BT * AS_STRIDE;     // [BK][WS_STRIDE]

    const int tid = threadIdx.x;
    const int tx  = tid & 15;    // expert group: experts 4*tx .. 4*tx+3
    const int ty  = tid >> 4;    // token group:  tokens  8*ty .. 8*ty+7
    const int tok0 = blockIdx.x * BT;

    float acc[8][4];
#pragma unroll
    for (int i = 0; i < 8; i++)
#pragma unroll
        for (int j = 0; j < 4; j++) acc[i][j] = 0.0f;

    for (int k0 = 0; k0 < DIM; k0 += BK) {
        __syncthreads();
        // load A tile: 64 rows x 16 cols = 256 float4, 2 per thread
#pragma unroll
        for (int q = 0; q < 2; q++) {
            int f4  = q * NTHREADS + tid;
            int row = f4 >> 2;
            int c4  = f4 & 3;
            float4 v = *reinterpret_cast<const float4*>(&A[(size_t)(tok0 + row) * DIM + k0 + c4 * 4]);
            *reinterpret_cast<float4*>(&As[row * AS_STRIDE + c4 * 4]) = v;
        }
        // load W tile transposed: 64 experts x 16 cols -> Ws[k][e]
#pragma unroll
        for (int q = 0; q < 2; q++) {
            int f4 = q * NTHREADS + tid;
            int e  = f4 >> 2;
            int c4 = f4 & 3;
            float4 v = *reinterpret_cast<const float4*>(&W[(size_t)e * DIM + k0 + c4 * 4]);
            Ws[(c4 * 4 + 0) * WS_STRIDE + e] = v.x;
            Ws[(c4 * 4 + 1) * WS_STRIDE + e] = v.y;
            Ws[(c4 * 4 + 2) * WS_STRIDE + e] = v.z;
            Ws[(c4 * 4 + 3) * WS_STRIDE + e] = v.w;
        }
        __syncthreads();

#pragma unroll
        for (int k4 = 0; k4 < BK; k4 += 4) {
            float wv[4][4];
#pragma unroll
            for (int kk = 0; kk < 4; kk++) {
                float4 w4 = *reinterpret_cast<const float4*>(&Ws[(k4 + kk) * WS_STRIDE + tx * 4]);
                wv[kk][0] = w4.x; wv[kk][1] = w4.y; wv[kk][2] = w4.z; wv[kk][3] = w4.w;
            }
#pragma unroll
            for (int i = 0; i < 8; i++) {
                float4 a4 = *reinterpret_cast<const float4*>(&As[(ty * 8 + i) * AS_STRIDE + k4]);
#pragma unroll
                for (int j = 0; j < 4; j++) {
                    acc[i][j] += a4.x * wv[0][j];
                    acc[i][j] += a4.y * wv[1][j];
                    acc[i][j] += a4.z * wv[2][j];
                    acc[i][j] += a4.w * wv[3][j];
                }
            }
        }
    }

    // ---- epilogue: logits -> smem, per-token argmax/softmax, histograms ----
    __syncthreads();
    float* Ls = smem;                      // [BT][LS_STRIDE]
#pragma unroll
    for (int i = 0; i < 8; i++)
#pragma unroll
        for (int j = 0; j < 4; j++)
            Ls[(ty * 8 + i) * LS_STRIDE + (tx * 4 + j)] = acc[i][j];
    if (tid < EXPERTS) cnt_s[tid] = 0;
    __syncthreads();

    if (tid < BT) {
        const int t = tid;
        float m = Ls[t * LS_STRIDE + 0];
        int   am = 0;
#pragma unroll 4
        for (int e = 1; e < EXPERTS; e++) {
            float v = Ls[t * LS_STRIDE + e];
            if (v > m) { m = v; am = e; }
        }
        float s = 0.0f;
#pragma unroll 4
        for (int e = 0; e < EXPERTS; e++)
            s += __expf(Ls[t * LS_STRIDE + e] - m);
        ms[t] = m;
        sums[t] = s;
        float gate = 1.0f / s;             // softmax value at the argmax
        int gt = tok0 + t;
        g_indices[gt]       = am;
        out[1 + gt]         = (float)am;   // indices
        out[1 + 2 * T + gt] = gate;        // gates
        atomicAdd(&cnt_s[am], 1);
    }
    __syncthreads();

    if (tid < EXPERTS) {
        const int e = tid;
        float acc_me = 0.0f;
#pragma unroll 4
        for (int t = 0; t < BT; t++)
            acc_me += __expf(Ls[t * LS_STRIDE + e] - ms[t]) / sums[t];
        atomicAdd(&g_me[e], acc_me);
        g_blockCounts[blockIdx.x * EXPERTS + e] = cnt_s[e];
    }
}

// ---------------- pass 2: exclusive scan over blocks + l_aux ----------------
__global__ void gate_scan(float* __restrict__ out, int T, int nB) {
    __shared__ float red[EXPERTS];
    const int e = threadIdx.x;   // 64 threads
    int run = 0;
    for (int b = 0; b < nB; b++) {
        g_blockOffsets[b * EXPERTS + e] = run;
        run += g_blockCounts[b * EXPERTS + e];
    }
    red[e] = g_me[e] * (float)run;
    __syncthreads();
    for (int s = EXPERTS / 2; s > 0; s >>= 1) {
        if (e < s) red[e] += red[e + s];
        __syncthreads();
    }
    if (e == 0)
        out[0] = red[0] * ((float)EXPERTS / ((float)T * (float)T));
}

// ---------------- pass 3: per-token location ----------------
__global__ void gate_loc(float* __restrict__ out, int T) {
    __shared__ int w0cnt[EXPERTS];
    const int b = blockIdx.x;
    const int t = threadIdx.x;           // 64 threads = 2 warps
    const int gt = b * BT + t;
    const int e = g_indices[gt];
    const int lane = t & 31;
    const int warp = t >> 5;

    w0cnt[t] = 0;
    __syncthreads();

    unsigned peers = __match_any_sync(0xffffffffu, e);
    int rank = __popc(peers & ((1u << lane) - 1u));
    if (warp == 0 && lane == (__ffs(peers) - 1))
        w0cnt[e] = __popc(peers);
    __syncthreads();

    int loc = g_blockOffsets[b * EXPERTS + e] + rank + (warp ? w0cnt[e] : 0);
    out[1 + T + gt] = (float)loc;
}

// ---------------- launch ----------------
extern "C" void kernel_launch(void* const* d_in, const int* in_sizes, int n_in,
                              void* d_out, int out_size) {
    const float* A = (const float*)d_in[0];
    const float* W = (const float*)d_in[1];
    float* out = (float*)d_out;
    const int T  = in_sizes[0] / DIM;   // 8192
    const int nB = T / BT;              // 128

    init_kernel<<<1, 64>>>();
    gate_main<<<nB, NTHREADS>>>(A, W, out, T);
    gate_scan<<<1, EXPERTS>>>(out, T, nB);
    gate_loc<<<nB, BT>>>(out, T);
}